// round 1
// baseline (speedup 1.0000x reference)
#include <cuda_runtime.h>

#define NN   50000
#define DEGQ 16
#define EE   (NN*DEGQ)
#define HH   32
#define FIN  128

// ---------------- scratch (device globals; no allocation) ----------------
__device__ float g_T[(size_t)EE*HH];       // T1 then (in-place) T2  : 102.4MB
__device__ float g_Asum[(size_t)NN*FIN];   // 25.6MB
__device__ float g_Asum1[NN*HH];
__device__ float g_u1[NN*HH];
__device__ float g_v1[NN*HH];
__device__ float g_s2[NN*HH];
__device__ float g_u2[NN*HH];
__device__ float g_v2[NN*HH];

// ---------------- f32x2 helpers ----------------
__device__ __forceinline__ void fma2(unsigned long long &acc, unsigned long long a, unsigned long long b) {
    asm("fma.rn.f32x2 %0, %1, %2, %0;" : "+l"(acc) : "l"(a), "l"(b));
}
__device__ __forceinline__ unsigned long long dup2(float a) {
    unsigned long long r;
    asm("mov.b64 %0, {%1, %1};" : "=l"(r) : "f"(a));
    return r;
}

// ============================================================================
// K1: per block: 8 nodes, 128 edges.
//   A[e][k] = |X[src][k]-X[dst][k]| (smem), Asum per node -> g_Asum,
//   T1 = A @ we1s^T -> g_T
// dyn smem: sW[128*36] + sA[128*132]
// ============================================================================
#define K1_SMEM_FLOATS (4608 + 128*132)
__global__ __launch_bounds__(256, 2) void k1(const float* __restrict__ X,
                                             const int*   __restrict__ dst,
                                             const float* __restrict__ we1s) {
    extern __shared__ float sm[];
    float* sW = sm;            // [k*36 + h]  (we1s transposed, padded)
    float* sA = sm + 4608;     // [e*132 + k]
    const int tid = threadIdx.x;
    const int blk = blockIdx.x;

    // load we1s (32x128) transposed into sW[k*36+h]
    #pragma unroll
    for (int r = 0; r < 16; r++) {
        int idx = tid + 256*r;
        int h = idx >> 7, k = idx & 127;
        sW[k*36 + h] = we1s[idx];
    }

    // phase B: warp w handles node blk*8+w; lane l covers k = 4l..4l+3
    const int w = tid >> 5, l = tid & 31;
    const int node = blk*8 + w;
    const float4 xv = ((const float4*)(X + (size_t)node*FIN))[l];
    float4 asum = make_float4(0.f,0.f,0.f,0.f);
    const int* de = dst + node*DEGQ;
    #pragma unroll
    for (int j = 0; j < DEGQ; j++) {
        int d = __ldg(de + j);
        float4 g = ((const float4*)(X + (size_t)d*FIN))[l];
        float4 a;
        a.x = fabsf(xv.x - g.x);
        a.y = fabsf(xv.y - g.y);
        a.z = fabsf(xv.z - g.z);
        a.w = fabsf(xv.w - g.w);
        asum.x += a.x; asum.y += a.y; asum.z += a.z; asum.w += a.w;
        *(float4*)&sA[(w*DEGQ + j)*132 + 4*l] = a;
    }
    *(float4*)&g_Asum[(size_t)node*FIN + 4*l] = asum;
    __syncthreads();

    // phase C: GEMM (128 x 128) @ (128 x 32) with f32x2
    const int tx = tid & 7;          // h0 = 4*tx
    const int ty = tid >> 3;         // rows ty, ty+32, ty+64, ty+96
    unsigned long long acc[4][2];
    #pragma unroll
    for (int i = 0; i < 4; i++) { acc[i][0] = 0ull; acc[i][1] = 0ull; }

    #pragma unroll 4
    for (int k0 = 0; k0 < FIN; k0 += 4) {
        ulonglong2 wv0 = *(const ulonglong2*)&sW[(k0+0)*36 + 4*tx];
        ulonglong2 wv1 = *(const ulonglong2*)&sW[(k0+1)*36 + 4*tx];
        ulonglong2 wv2 = *(const ulonglong2*)&sW[(k0+2)*36 + 4*tx];
        ulonglong2 wv3 = *(const ulonglong2*)&sW[(k0+3)*36 + 4*tx];
        #pragma unroll
        for (int i = 0; i < 4; i++) {
            float4 av = *(const float4*)&sA[(ty + 32*i)*132 + k0];
            unsigned long long a0 = dup2(av.x);
            fma2(acc[i][0], a0, wv0.x); fma2(acc[i][1], a0, wv0.y);
            unsigned long long a1 = dup2(av.y);
            fma2(acc[i][0], a1, wv1.x); fma2(acc[i][1], a1, wv1.y);
            unsigned long long a2 = dup2(av.z);
            fma2(acc[i][0], a2, wv2.x); fma2(acc[i][1], a2, wv2.y);
            unsigned long long a3 = dup2(av.w);
            fma2(acc[i][0], a3, wv3.x); fma2(acc[i][1], a3, wv3.y);
        }
    }
    const size_t ebase = (size_t)blk*128;
    #pragma unroll
    for (int i = 0; i < 4; i++) {
        ulonglong2 v; v.x = acc[i][0]; v.y = acc[i][1];
        *(ulonglong2*)&g_T[(ebase + ty + 32*i)*HH + 4*tx] = v;
    }
}

// ============================================================================
// K1b: node-level: Xn1 = relu((Asum/D)@wn1p^T + bn1p + bn1s)
//      u1 = Xn1@P1^T + be1p + be1s ; v1 = Xn1@Q1^T ; s2 = Xn1@wn2s^T + bn2p + bn2s
// 1024 threads, 32 nodes/block
// ============================================================================
__global__ __launch_bounds__(1024, 1) void k1b(const float* __restrict__ D,
        const float* __restrict__ wn1p, const float* __restrict__ bn1p,
        const float* __restrict__ bn1s, const float* __restrict__ we1p,
        const float* __restrict__ be1p, const float* __restrict__ be1s,
        const float* __restrict__ wn2s, const float* __restrict__ bn2p,
        const float* __restrict__ bn2s) {
    __shared__ float sAs[32*128];          // Asum rows; later aliased as Xn1[32*33]
    __shared__ float sWp[128*32];          // wn1p transposed [k*32+h]
    __shared__ float sP[32*32], sQ[32*32], sW2[32*32];
    const int tid = threadIdx.x;
    const int i_loc = tid >> 5, h = tid & 31;
    const int node0 = blockIdx.x * 32;
    const int node = node0 + i_loc;
    const bool valid = node < NN;

    if (node0 + (tid >> 5) < NN)
        ((float4*)sAs)[tid] = ((const float4*)(g_Asum + (size_t)node0*FIN))[tid];
    #pragma unroll
    for (int r = 0; r < 4; r++) {
        int idx = tid + 1024*r;
        int hh = idx >> 7, k = idx & 127;
        sWp[k*32 + hh] = wn1p[idx];
    }
    {
        int hh = tid >> 5, h2 = tid & 31;
        float wa = we1p[hh*64 + h2], wb = we1p[hh*64 + 32 + h2];
        sP[h2*32 + hh] = 0.5f*(wa + wb);
        sQ[h2*32 + hh] = 0.5f*(wb - wa);
        sW2[h2*32 + hh] = wn2s[hh*32 + h2];
    }
    __syncthreads();

    const float invD = valid ? 1.0f/__ldg(D + node) : 0.f;
    float s = 0.f;
    #pragma unroll 8
    for (int k = 0; k < FIN; k++)
        s += sAs[i_loc*FIN + k] * sWp[k*32 + h];
    float x = fmaxf(s*invD + __ldg(bn1p+h) + __ldg(bn1s+h), 0.f);
    __syncthreads();                 // done reading sAs
    float* sXn1 = sAs;               // alias
    sXn1[i_loc*33 + h] = x;
    __syncthreads();

    float u = __ldg(be1p+h) + __ldg(be1s+h);
    float v = 0.f;
    float s2 = __ldg(bn2p+h) + __ldg(bn2s+h);
    #pragma unroll
    for (int h2 = 0; h2 < 32; h2++) {
        float xx = sXn1[i_loc*33 + h2];
        u  += xx * sP[h2*32 + h];
        v  += xx * sQ[h2*32 + h];
        s2 += xx * sW2[h2*32 + h];
    }
    if (valid) {
        g_u1[node*HH + h] = u;
        g_v1[node*HH + h] = v;
        g_s2[node*HH + h] = s2;
    }
}

// ============================================================================
// K2: per block: 8 nodes / 128 edges.
//   vals1 = relu(u1[src] + v1[dst] + T1) ; Asum1 -> g_Asum1
//   T2 = vals1 @ we2s^T  -> g_T (in place)
// ============================================================================
__global__ __launch_bounds__(256) void k2(const int* __restrict__ dst,
                                          const float* __restrict__ we2s) {
    __shared__ float sV[128*33];
    __shared__ float sW[32*36];
    const int tid = threadIdx.x, blk = blockIdx.x;
    #pragma unroll
    for (int r = 0; r < 4; r++) {
        int idx = tid + 256*r;
        int hh = idx >> 5, h2 = idx & 31;
        sW[h2*36 + hh] = we2s[idx];
    }
    const int w = tid >> 5, h = tid & 31;
    const int node = blk*8 + w;
    const float u1h = g_u1[node*HH + h];
    float asum = 0.f;
    const int* de = dst + node*DEGQ;
    const size_t ebase = (size_t)node*DEGQ;
    #pragma unroll
    for (int j = 0; j < DEGQ; j++) {
        int d = __ldg(de + j);
        float val = u1h + g_v1[d*HH + h] + g_T[(ebase + j)*HH + h];
        val = fmaxf(val, 0.f);
        asum += val;
        sV[(w*DEGQ + j)*33 + h] = val;
    }
    g_Asum1[node*HH + h] = asum;
    __syncthreads();

    const int tx = tid & 7, ty = tid >> 3;
    unsigned long long acc[4][2];
    #pragma unroll
    for (int i = 0; i < 4; i++) { acc[i][0] = 0ull; acc[i][1] = 0ull; }
    #pragma unroll 4
    for (int h2 = 0; h2 < 32; h2++) {
        ulonglong2 wv = *(const ulonglong2*)&sW[h2*36 + 4*tx];
        #pragma unroll
        for (int i = 0; i < 4; i++) {
            unsigned long long a2 = dup2(sV[(ty + 32*i)*33 + h2]);
            fma2(acc[i][0], a2, wv.x);
            fma2(acc[i][1], a2, wv.y);
        }
    }
    const size_t tb = (size_t)blk*128;
    #pragma unroll
    for (int i = 0; i < 4; i++) {
        ulonglong2 v; v.x = acc[i][0]; v.y = acc[i][1];
        *(ulonglong2*)&g_T[(tb + ty + 32*i)*HH + 4*tx] = v;
    }
}

// ============================================================================
// K2b: node-level: Xn2 = relu((Asum1/D)@wn2p^T + s2) ; u2/v2 from we2p
// ============================================================================
__global__ __launch_bounds__(1024, 1) void k2b(const float* __restrict__ D,
        const float* __restrict__ wn2p, const float* __restrict__ we2p,
        const float* __restrict__ be2p, const float* __restrict__ be2s) {
    __shared__ float sAs[32*33];
    __shared__ float sWp[32*32], sP[32*32], sQ[32*32];
    __shared__ float sXn2[32*33];
    const int tid = threadIdx.x;
    const int i_loc = tid >> 5, h = tid & 31;
    const int node0 = blockIdx.x*32, node = node0 + i_loc;
    const bool valid = node < NN;
    if (valid) sAs[i_loc*33 + h] = g_Asum1[node*HH + h];
    {
        int hh = tid >> 5, h2 = tid & 31;
        sWp[h2*32 + hh] = wn2p[hh*32 + h2];
        float wa = we2p[hh*64 + h2], wb = we2p[hh*64 + 32 + h2];
        sP[h2*32 + hh] = 0.5f*(wa+wb);
        sQ[h2*32 + hh] = 0.5f*(wb-wa);
    }
    __syncthreads();
    const float invD = valid ? 1.f/__ldg(D+node) : 0.f;
    float s = 0.f;
    #pragma unroll
    for (int h2 = 0; h2 < 32; h2++)
        s += sAs[i_loc*33 + h2] * sWp[h2*32 + h];
    const float sg = valid ? g_s2[node*HH + h] : 0.f;
    float x = fmaxf(s*invD + sg, 0.f);
    sXn2[i_loc*33 + h] = x;
    __syncthreads();
    float u = __ldg(be2p+h) + __ldg(be2s+h), v = 0.f;
    #pragma unroll
    for (int h2 = 0; h2 < 32; h2++) {
        float xx = sXn2[i_loc*33 + h2];
        u += xx * sP[h2*32 + h];
        v += xx * sQ[h2*32 + h];
    }
    if (valid) {
        g_u2[node*HH + h] = u;
        g_v2[node*HH + h] = v;
    }
}

// ============================================================================
// K3: out[e] = sigmoid( sum_h relu(u2[src]+v2[dst]+T2[e])*wc[h] + bc )
// warp handles 32 edges; batched sigmoid (one per lane at the end)
// ============================================================================
__global__ __launch_bounds__(256) void k3(const int* __restrict__ dst,
                                          const float* __restrict__ wc,
                                          const float* __restrict__ bc,
                                          float* __restrict__ out) {
    const int tid = threadIdx.x, w = tid >> 5, l = tid & 31;
    const size_t e0 = (size_t)blockIdx.x*256 + (size_t)w*32;
    const float wch = __ldg(wc + l);
    float res = 0.f;
    #pragma unroll 4
    for (int m = 0; m < 32; m++) {
        const size_t e = e0 + m;
        const int s = (int)(e >> 4);
        const int d = __ldg(dst + e);
        float val = g_u2[s*HH + l] + g_v2[d*HH + l] + g_T[e*HH + l];
        val = fmaxf(val, 0.f);
        float c = val * wch;
        c += __shfl_xor_sync(0xffffffffu, c, 16);
        c += __shfl_xor_sync(0xffffffffu, c, 8);
        c += __shfl_xor_sync(0xffffffffu, c, 4);
        c += __shfl_xor_sync(0xffffffffu, c, 2);
        c += __shfl_xor_sync(0xffffffffu, c, 1);
        if (l == m) res = c;
    }
    const float x = res + __ldg(bc);
    out[e0 + l] = 1.f / (1.f + __expf(-x));
}

// ============================================================================
extern "C" void kernel_launch(void* const* d_in, const int* in_sizes, int n_in,
                              void* d_out, int out_size) {
    const float* X    = (const float*)d_in[0];
    const int*   dst  = (const int*)  d_in[2];
    const float* D    = (const float*)d_in[3];
    const float* wn1p = (const float*)d_in[4];
    const float* bn1p = (const float*)d_in[5];
    const float* bn1s = (const float*)d_in[7];
    const float* we1p = (const float*)d_in[8];
    const float* be1p = (const float*)d_in[9];
    const float* we1s = (const float*)d_in[10];
    const float* be1s = (const float*)d_in[11];
    const float* wn2p = (const float*)d_in[12];
    const float* bn2p = (const float*)d_in[13];
    const float* wn2s = (const float*)d_in[14];
    const float* bn2s = (const float*)d_in[15];
    const float* we2p = (const float*)d_in[16];
    const float* be2p = (const float*)d_in[17];
    const float* we2s = (const float*)d_in[18];
    const float* be2s = (const float*)d_in[19];
    const float* wc   = (const float*)d_in[20];
    const float* bc   = (const float*)d_in[21];
    float* out = (float*)d_out;

    const int smem1 = K1_SMEM_FLOATS * 4;
    cudaFuncSetAttribute(k1, cudaFuncAttributeMaxDynamicSharedMemorySize, smem1);

    k1 <<<NN/8, 256, smem1>>>(X, dst, we1s);
    k1b<<<(NN+31)/32, 1024>>>(D, wn1p, bn1p, bn1s, we1p, be1p, be1s, wn2s, bn2p, bn2s);
    k2 <<<NN/8, 256>>>(dst, we2s);
    k2b<<<(NN+31)/32, 1024>>>(D, wn2p, we2p, be2p, be2s);
    k3 <<<EE/256, 256>>>(dst, wc, bc, out);
}

// round 2
// speedup vs baseline: 1.2384x; 1.2384x over previous
#include <cuda_runtime.h>

#define NN   50000
#define DEGQ 16
#define EE   (NN*DEGQ)
#define HH   32
#define FIN  128

// ---------------- scratch (device globals; no allocation) ----------------
__device__ float g_T[(size_t)EE*HH];       // T1 then (in-place) T2  : 102.4MB
__device__ float g_u1[NN*HH];
__device__ float g_v1[NN*HH];
__device__ float g_s2[NN*HH];
__device__ float g_u2[NN*HH];
__device__ float g_v2[NN*HH];

// ---------------- f32x2 helpers ----------------
__device__ __forceinline__ void fma2(unsigned long long &acc, unsigned long long a, unsigned long long b) {
    asm("fma.rn.f32x2 %0, %1, %2, %0;" : "+l"(acc) : "l"(a), "l"(b));
}
__device__ __forceinline__ unsigned long long dup2(float a) {
    unsigned long long r;
    asm("mov.b64 %0, {%1, %1};" : "=l"(r) : "f"(a));
    return r;
}

// ============================================================================
// K1 (fused edge layer 1 + node layer): per block 8 nodes / 128 edges.
//   A[e][k] = |X[src][k]-X[dst][k]| (smem), asum per node in regs,
//   T1 = A @ we1s^T -> g_T
//   tail: Xn1 = relu((asum/D)@wn1p^T + b), then u1/v1/s2 via shfl broadcast.
// dyn smem: sW[128*36] + sA[128*132]  (tail reuses sA)
// ============================================================================
#define K1_SMEM_FLOATS (4608 + 128*132)
__global__ __launch_bounds__(256, 2) void k1(const float* __restrict__ X,
                                             const int*   __restrict__ dst,
                                             const float* __restrict__ D,
                                             const float* __restrict__ we1s,
                                             const float* __restrict__ wn1p,
                                             const float* __restrict__ bn1p,
                                             const float* __restrict__ bn1s,
                                             const float* __restrict__ we1p,
                                             const float* __restrict__ be1p,
                                             const float* __restrict__ be1s,
                                             const float* __restrict__ wn2s,
                                             const float* __restrict__ bn2p,
                                             const float* __restrict__ bn2s) {
    extern __shared__ float sm[];
    float* sW = sm;            // [k*36 + h]  (we1s transposed, padded)
    float* sA = sm + 4608;     // [e*132 + k]
    const int tid = threadIdx.x;
    const int blk = blockIdx.x;

    // load we1s (32x128) transposed into sW[k*36+h]
    #pragma unroll
    for (int r = 0; r < 16; r++) {
        int idx = tid + 256*r;
        int h = idx >> 7, k = idx & 127;
        sW[k*36 + h] = __ldg(we1s + idx);
    }

    // phase B: warp w handles node blk*8+w; lane l covers k = 4l..4l+3
    const int w = tid >> 5, l = tid & 31;
    const int node = blk*8 + w;
    const float4 xv = ((const float4*)(X + (size_t)node*FIN))[l];
    float4 asum = make_float4(0.f,0.f,0.f,0.f);
    const int* de = dst + node*DEGQ;
    #pragma unroll
    for (int j = 0; j < DEGQ; j++) {
        int d = __ldg(de + j);
        float4 g = ((const float4*)(X + (size_t)d*FIN))[l];
        float4 a;
        a.x = fabsf(xv.x - g.x);
        a.y = fabsf(xv.y - g.y);
        a.z = fabsf(xv.z - g.z);
        a.w = fabsf(xv.w - g.w);
        asum.x += a.x; asum.y += a.y; asum.z += a.z; asum.w += a.w;
        *(float4*)&sA[(w*DEGQ + j)*132 + 4*l] = a;
    }
    __syncthreads();

    // phase C: GEMM (128 x 128) @ (128 x 32) with f32x2
    const int tx = tid & 7;          // h0 = 4*tx
    const int ty = tid >> 3;         // rows ty, ty+32, ty+64, ty+96
    unsigned long long acc[4][2];
    #pragma unroll
    for (int i = 0; i < 4; i++) { acc[i][0] = 0ull; acc[i][1] = 0ull; }

    #pragma unroll 4
    for (int k0 = 0; k0 < FIN; k0 += 4) {
        ulonglong2 wv0 = *(const ulonglong2*)&sW[(k0+0)*36 + 4*tx];
        ulonglong2 wv1 = *(const ulonglong2*)&sW[(k0+1)*36 + 4*tx];
        ulonglong2 wv2 = *(const ulonglong2*)&sW[(k0+2)*36 + 4*tx];
        ulonglong2 wv3 = *(const ulonglong2*)&sW[(k0+3)*36 + 4*tx];
        #pragma unroll
        for (int i = 0; i < 4; i++) {
            float4 av = *(const float4*)&sA[(ty + 32*i)*132 + k0];
            unsigned long long a0 = dup2(av.x);
            fma2(acc[i][0], a0, wv0.x); fma2(acc[i][1], a0, wv0.y);
            unsigned long long a1 = dup2(av.y);
            fma2(acc[i][0], a1, wv1.x); fma2(acc[i][1], a1, wv1.y);
            unsigned long long a2 = dup2(av.z);
            fma2(acc[i][0], a2, wv2.x); fma2(acc[i][1], a2, wv2.y);
            unsigned long long a3 = dup2(av.w);
            fma2(acc[i][0], a3, wv3.x); fma2(acc[i][1], a3, wv3.y);
        }
    }
    const size_t ebase = (size_t)blk*128;
    #pragma unroll
    for (int i = 0; i < 4; i++) {
        ulonglong2 v; v.x = acc[i][0]; v.y = acc[i][1];
        *(ulonglong2*)&g_T[(ebase + ty + 32*i)*HH + 4*tx] = v;
    }
    __syncthreads();   // all reads of sA done; reuse it for the tail

    // ---- tail: node-level layer-1 + precompute u1/v1/s2 ----
    float* sAs2 = sA;                 // [8][132] asum rows
    float* sWn  = sA + 1056;          // wn1p^T [k*33 + h]  (4224)
    float* sP   = sA + 5280;          // [h2*33 + h]
    float* sQ   = sP + 1056;
    float* sW2  = sQ + 1056;

    *(float4*)&sAs2[w*132 + 4*l] = asum;
    #pragma unroll
    for (int r = 0; r < 16; r++) {
        int idx = tid + 256*r;
        int hh = idx >> 7, k = idx & 127;
        sWn[k*33 + hh] = __ldg(wn1p + idx);      // stride-33 stores: conflict-free
    }
    #pragma unroll
    for (int r = 0; r < 4; r++) {
        int idx = tid + 256*r;
        int hh = idx >> 5, h2 = idx & 31;
        float wa = __ldg(we1p + hh*64 + h2);
        float wb = __ldg(we1p + hh*64 + 32 + h2);
        sP[h2*33 + hh] = 0.5f*(wa + wb);
        sQ[h2*33 + hh] = 0.5f*(wb - wa);
        sW2[h2*33 + hh] = __ldg(wn2s + idx);
    }
    __syncthreads();

    // warp w = node, lane l = output h
    const float invD = 1.0f / __ldg(D + node);
    float s = 0.f;
    #pragma unroll
    for (int k0 = 0; k0 < FIN; k0 += 4) {
        float4 av = *(const float4*)&sAs2[w*132 + k0];
        s = fmaf(av.x, sWn[(k0+0)*33 + l], s);
        s = fmaf(av.y, sWn[(k0+1)*33 + l], s);
        s = fmaf(av.z, sWn[(k0+2)*33 + l], s);
        s = fmaf(av.w, sWn[(k0+3)*33 + l], s);
    }
    float x = fmaxf(fmaf(s, invD, __ldg(bn1p+l) + __ldg(bn1s+l)), 0.f);

    float u  = __ldg(be1p+l) + __ldg(be1s+l);
    float vv = 0.f;
    float s2 = __ldg(bn2p+l) + __ldg(bn2s+l);
    #pragma unroll
    for (int h2 = 0; h2 < 32; h2++) {
        float xx = __shfl_sync(0xffffffffu, x, h2);
        u  = fmaf(xx, sP[h2*33 + l], u);
        vv = fmaf(xx, sQ[h2*33 + l], vv);
        s2 = fmaf(xx, sW2[h2*33 + l], s2);
    }
    g_u1[node*HH + l] = u;
    g_v1[node*HH + l] = vv;
    g_s2[node*HH + l] = s2;
}

// ============================================================================
// K2 (fused edge layer 2 GEMM + node layer 2): per block 8 nodes / 128 edges.
//   vals1 = relu(u1[src] + v1[dst] + T1); asum per lane
//   T2 = vals1 @ we2s^T -> g_T (in place)
//   tail: Xn2 = relu((asum/D)@wn2p^T + s2); u2/v2 via shfl broadcast.
// ============================================================================
__global__ __launch_bounds__(256) void k2(const int* __restrict__ dst,
                                          const float* __restrict__ D,
                                          const float* __restrict__ we2s,
                                          const float* __restrict__ wn2p,
                                          const float* __restrict__ we2p,
                                          const float* __restrict__ be2p,
                                          const float* __restrict__ be2s) {
    __shared__ float sV[128*33];
    __shared__ float sW[32*36];
    __shared__ float sWn[32*33];
    __shared__ float sP[32*33];
    __shared__ float sQ[32*33];
    const int tid = threadIdx.x, blk = blockIdx.x;
    #pragma unroll
    for (int r = 0; r < 4; r++) {
        int idx = tid + 256*r;
        int hh = idx >> 5, h2 = idx & 31;
        sW[h2*36 + hh]  = __ldg(we2s + idx);
        sWn[h2*33 + hh] = __ldg(wn2p + idx);
        float wa = __ldg(we2p + hh*64 + h2);
        float wb = __ldg(we2p + hh*64 + 32 + h2);
        sP[h2*33 + hh] = 0.5f*(wa + wb);
        sQ[h2*33 + hh] = 0.5f*(wb - wa);
    }
    const int w = tid >> 5, h = tid & 31;
    const int node = blk*8 + w;
    const float u1h = g_u1[node*HH + h];
    float asum = 0.f;
    const int* de = dst + node*DEGQ;
    const size_t ebase = (size_t)node*DEGQ;
    __syncthreads();
    #pragma unroll
    for (int j = 0; j < DEGQ; j++) {
        int d = __ldg(de + j);
        float val = u1h + g_v1[d*HH + h] + g_T[(ebase + j)*HH + h];
        val = fmaxf(val, 0.f);
        asum += val;
        sV[(w*DEGQ + j)*33 + h] = val;
    }
    __syncthreads();

    // GEMM: T2 = vals1 @ we2s^T
    const int tx = tid & 7, ty = tid >> 3;
    unsigned long long acc[4][2];
    #pragma unroll
    for (int i = 0; i < 4; i++) { acc[i][0] = 0ull; acc[i][1] = 0ull; }
    #pragma unroll 4
    for (int h2 = 0; h2 < 32; h2++) {
        ulonglong2 wv = *(const ulonglong2*)&sW[h2*36 + 4*tx];
        #pragma unroll
        for (int i = 0; i < 4; i++) {
            unsigned long long a2 = dup2(sV[(ty + 32*i)*33 + h2]);
            fma2(acc[i][0], a2, wv.x);
            fma2(acc[i][1], a2, wv.y);
        }
    }
    const size_t tb = (size_t)blk*128;
    #pragma unroll
    for (int i = 0; i < 4; i++) {
        ulonglong2 v; v.x = acc[i][0]; v.y = acc[i][1];
        *(ulonglong2*)&g_T[(tb + ty + 32*i)*HH + 4*tx] = v;
    }

    // ---- tail: node layer 2 + u2/v2 (warp-local; asum lives in lane h) ----
    const float invD = 1.0f / __ldg(D + node);
    float s = 0.f;
    #pragma unroll
    for (int h2 = 0; h2 < 32; h2++) {
        float aa = __shfl_sync(0xffffffffu, asum, h2);
        s = fmaf(aa, sWn[h2*33 + h], s);
    }
    float x = fmaxf(fmaf(s, invD, g_s2[node*HH + h]), 0.f);
    float u = __ldg(be2p+h) + __ldg(be2s+h), vv = 0.f;
    #pragma unroll
    for (int h2 = 0; h2 < 32; h2++) {
        float xx = __shfl_sync(0xffffffffu, x, h2);
        u  = fmaf(xx, sP[h2*33 + h], u);
        vv = fmaf(xx, sQ[h2*33 + h], vv);
    }
    g_u2[node*HH + h] = u;
    g_v2[node*HH + h] = vv;
}

// ============================================================================
// K3: out[e] = sigmoid( sum_h relu(u2[src]+v2[dst]+T2[e])*wc[h] + bc )
// ============================================================================
__global__ __launch_bounds__(256) void k3(const int* __restrict__ dst,
                                          const float* __restrict__ wc,
                                          const float* __restrict__ bc,
                                          float* __restrict__ out) {
    const int tid = threadIdx.x, w = tid >> 5, l = tid & 31;
    const size_t e0 = (size_t)blockIdx.x*256 + (size_t)w*32;
    const float wch = __ldg(wc + l);
    float res = 0.f;
    #pragma unroll 4
    for (int m = 0; m < 32; m++) {
        const size_t e = e0 + m;
        const int s = (int)(e >> 4);
        const int d = __ldg(dst + e);
        float val = g_u2[s*HH + l] + g_v2[d*HH + l] + g_T[e*HH + l];
        val = fmaxf(val, 0.f);
        float c = val * wch;
        c += __shfl_xor_sync(0xffffffffu, c, 16);
        c += __shfl_xor_sync(0xffffffffu, c, 8);
        c += __shfl_xor_sync(0xffffffffu, c, 4);
        c += __shfl_xor_sync(0xffffffffu, c, 2);
        c += __shfl_xor_sync(0xffffffffu, c, 1);
        if (l == m) res = c;
    }
    const float x = res + __ldg(bc);
    out[e0 + l] = 1.f / (1.f + __expf(-x));
}

// ============================================================================
extern "C" void kernel_launch(void* const* d_in, const int* in_sizes, int n_in,
                              void* d_out, int out_size) {
    const float* X    = (const float*)d_in[0];
    const int*   dst  = (const int*)  d_in[2];
    const float* D    = (const float*)d_in[3];
    const float* wn1p = (const float*)d_in[4];
    const float* bn1p = (const float*)d_in[5];
    const float* bn1s = (const float*)d_in[7];
    const float* we1p = (const float*)d_in[8];
    const float* be1p = (const float*)d_in[9];
    const float* we1s = (const float*)d_in[10];
    const float* be1s = (const float*)d_in[11];
    const float* wn2p = (const float*)d_in[12];
    const float* bn2p = (const float*)d_in[13];
    const float* wn2s = (const float*)d_in[14];
    const float* bn2s = (const float*)d_in[15];
    const float* we2p = (const float*)d_in[16];
    const float* be2p = (const float*)d_in[17];
    const float* we2s = (const float*)d_in[18];
    const float* be2s = (const float*)d_in[19];
    const float* wc   = (const float*)d_in[20];
    const float* bc   = (const float*)d_in[21];
    float* out = (float*)d_out;

    const int smem1 = K1_SMEM_FLOATS * 4;
    cudaFuncSetAttribute(k1, cudaFuncAttributeMaxDynamicSharedMemorySize, smem1);

    k1 <<<NN/8, 256, smem1>>>(X, dst, D, we1s, wn1p, bn1p, bn1s,
                              we1p, be1p, be1s, wn2s, bn2p, bn2s);
    k2 <<<NN/8, 256>>>(dst, D, we2s, wn2p, we2p, be2p, be2s);
    k3 <<<EE/256, 256>>>(dst, wc, bc, out);
}

// round 5
// speedup vs baseline: 1.5085x; 1.2181x over previous
#include <cuda_runtime.h>
#include <cuda_bf16.h>
#include <cstdint>

#define NN   50000
#define DEGQ 16
#define EE   (NN*DEGQ)
#define HH   32
#define FIN  128

// ---------------- scratch (device globals; no allocation) ----------------
__device__ float g_T[(size_t)EE*HH];       // T1 then (in-place) T2  : 102.4MB
__device__ float g_u1[NN*HH];
__device__ float g_v1[NN*HH];
__device__ float g_s2[NN*HH];
__device__ float g_u2[NN*HH];
__device__ float g_v2[NN*HH];

// ---------------- f32x2 helpers (k2 uses them) ----------------
__device__ __forceinline__ void fma2(unsigned long long &acc, unsigned long long a, unsigned long long b) {
    asm("fma.rn.f32x2 %0, %1, %2, %0;" : "+l"(acc) : "l"(a), "l"(b));
}
__device__ __forceinline__ unsigned long long dup2(float a) {
    unsigned long long r;
    asm("mov.b64 %0, {%1, %1};" : "=l"(r) : "f"(a));
    return r;
}

// ---------------- mma.sync helpers (sm_80+ baseline ISA; no tcgen05) ------
__device__ __forceinline__ uint32_t smem_u32(const void* p) {
    uint32_t a;
    asm("{ .reg .u64 t; cvta.to.shared.u64 t, %1; cvt.u32.u64 %0, t; }" : "=r"(a) : "l"(p));
    return a;
}
__device__ __forceinline__ void ldsm4(uint32_t* r, uint32_t addr) {
    asm volatile("ldmatrix.sync.aligned.m8n8.x4.shared.b16 {%0,%1,%2,%3}, [%4];"
        : "=r"(r[0]), "=r"(r[1]), "=r"(r[2]), "=r"(r[3]) : "r"(addr));
}
__device__ __forceinline__ void ldsm2(uint32_t* r, uint32_t addr) {
    asm volatile("ldmatrix.sync.aligned.m8n8.x2.shared.b16 {%0,%1}, [%2];"
        : "=r"(r[0]), "=r"(r[1]) : "r"(addr));
}
__device__ __forceinline__ void mma_bf16(float* c, const uint32_t* a, const uint32_t* b) {
    asm volatile("mma.sync.aligned.m16n8k16.row.col.f32.bf16.bf16.f32 "
        "{%0,%1,%2,%3}, {%4,%5,%6,%7}, {%8,%9}, {%0,%1,%2,%3};"
        : "+f"(c[0]), "+f"(c[1]), "+f"(c[2]), "+f"(c[3])
        : "r"(a[0]), "r"(a[1]), "r"(a[2]), "r"(a[3]), "r"(b[0]), "r"(b[1]));
}

// k1 dynamic smem layout (bytes). Row pitch 272B (136 bf16): 272 mod 128 = 16
// -> ldmatrix 8-row groups hit 8 distinct 16B segments of the 128B bank cycle.
#define PITCH    272
#define OFF_A1   0
#define OFF_A2   (128*PITCH)            // 34816
#define OFF_W1   (2*128*PITCH)          // 69632
#define OFF_W2   (OFF_W1 + 32*PITCH)    // 78336
#define K1_SMEM  (OFF_W2 + 32*PITCH)    // 87040
// tail region (floats, aliases A1/A2 after MMA epilogue)
#define TL_AS   0
#define TL_WN   (TL_AS + 8*132)
#define TL_P    (TL_WN + 128*33)
#define TL_Q    (TL_P + 32*33)
#define TL_W2   (TL_Q + 32*33)

// ============================================================================
// K1 (HMMA tensor path): per block 8 nodes / 128 edges.
//   A[e][k] = |X[src][k]-X[dst][k]| -> bf16 split A1+A2 in smem
//   W = we1s -> bf16 split W1+W2 in smem
//   T1 = A1W1 + A1W2 + A2W1 via mma.sync (fp32 accum in regs) -> g_T
//   asum per node in regs; tail: Xn1 -> u1/v1/s2 via shfl broadcast.
// ============================================================================
__global__ __launch_bounds__(256, 2) void k1(const float* __restrict__ X,
                                             const int*   __restrict__ dst,
                                             const float* __restrict__ D,
                                             const float* __restrict__ we1s,
                                             const float* __restrict__ wn1p,
                                             const float* __restrict__ bn1p,
                                             const float* __restrict__ bn1s,
                                             const float* __restrict__ we1p,
                                             const float* __restrict__ be1p,
                                             const float* __restrict__ be1s,
                                             const float* __restrict__ wn2s,
                                             const float* __restrict__ bn2p,
                                             const float* __restrict__ bn2s) {
    extern __shared__ unsigned char smb[];
    float* sf = (float*)smb;
    const uint32_t sb = smem_u32(smb);

    const int tid = threadIdx.x;
    const int blk = blockIdx.x;
    const int w = tid >> 5, l = tid & 31;

    // ---- W convert: we1s (32 x 128 fp32) -> W1,W2 bf16 ----
    #pragma unroll
    for (int r = 0; r < 16; r++) {
        int idx = tid + 256*r;
        int h = idx >> 7, k = idx & 127;
        float wv = __ldg(we1s + idx);
        __nv_bfloat16 w1 = __float2bfloat16(wv);
        __nv_bfloat16 w2 = __float2bfloat16(wv - __bfloat162float(w1));
        uint32_t o = h*PITCH + 2*k;
        *(__nv_bfloat16*)(smb + OFF_W1 + o) = w1;
        *(__nv_bfloat16*)(smb + OFF_W2 + o) = w2;
    }

    // ---- phase B: gather, abs-diff, fp32 asum, bf16 split stores ----
    const int node = blk*8 + w;
    const float4 xv = ((const float4*)(X + (size_t)node*FIN))[l];
    float4 asum = make_float4(0.f, 0.f, 0.f, 0.f);
    const int* de = dst + node*DEGQ;
    #pragma unroll
    for (int j = 0; j < DEGQ; j++) {
        int d = __ldg(de + j);
        float4 g = ((const float4*)(X + (size_t)d*FIN))[l];
        float4 a;
        a.x = fabsf(xv.x - g.x);
        a.y = fabsf(xv.y - g.y);
        a.z = fabsf(xv.z - g.z);
        a.w = fabsf(xv.w - g.w);
        asum.x += a.x; asum.y += a.y; asum.z += a.z; asum.w += a.w;

        __nv_bfloat16 h0 = __float2bfloat16(a.x);
        __nv_bfloat16 h1 = __float2bfloat16(a.y);
        __nv_bfloat16 h2 = __float2bfloat16(a.z);
        __nv_bfloat16 h3 = __float2bfloat16(a.w);
        __nv_bfloat16 r0 = __float2bfloat16(a.x - __bfloat162float(h0));
        __nv_bfloat16 r1 = __float2bfloat16(a.y - __bfloat162float(h1));
        __nv_bfloat16 r2 = __float2bfloat16(a.z - __bfloat162float(h2));
        __nv_bfloat16 r3 = __float2bfloat16(a.w - __bfloat162float(h3));

        __nv_bfloat162 p01 = __halves2bfloat162(h0, h1);
        __nv_bfloat162 p23 = __halves2bfloat162(h2, h3);
        __nv_bfloat162 q01 = __halves2bfloat162(r0, r1);
        __nv_bfloat162 q23 = __halves2bfloat162(r2, r3);
        uint64_t hiw = (uint64_t)(*(uint32_t*)&p01) | ((uint64_t)(*(uint32_t*)&p23) << 32);
        uint64_t low = (uint64_t)(*(uint32_t*)&q01) | ((uint64_t)(*(uint32_t*)&q23) << 32);

        const int row = w*DEGQ + j;
        uint32_t o = row*PITCH + l*8;          // element 4l, byte 8l
        *(uint64_t*)(smb + OFF_A1 + o) = hiw;
        *(uint64_t*)(smb + OFF_A2 + o) = low;
    }
    __syncthreads();

    // ---- MMA: warp w handles rows wr..wr+15, all 32 output cols ----
    {
        const int wr = w*16;
        float c[4][4];
        #pragma unroll
        for (int nt = 0; nt < 4; nt++)
            c[nt][0] = c[nt][1] = c[nt][2] = c[nt][3] = 0.f;

        const uint32_t a_lane_off = (uint32_t)((wr + (l & 15))*PITCH + (l >> 4)*16);
        const uint32_t b_lane_off = (uint32_t)(((l & 7))*PITCH + ((l >> 3) & 1)*16);

        #pragma unroll
        for (int ks = 0; ks < 8; ks++) {
            uint32_t kb = ks*32;
            uint32_t a1[4], a2[4];
            ldsm4(a1, sb + OFF_A1 + a_lane_off + kb);
            ldsm4(a2, sb + OFF_A2 + a_lane_off + kb);
            #pragma unroll
            for (int nt = 0; nt < 4; nt++) {
                uint32_t b1[2], b2[2];
                uint32_t bo = b_lane_off + (uint32_t)(nt*8*PITCH) + kb;
                ldsm2(b1, sb + OFF_W1 + bo);
                ldsm2(b2, sb + OFF_W2 + bo);
                mma_bf16(c[nt], a1, b1);
                mma_bf16(c[nt], a1, b2);
                mma_bf16(c[nt], a2, b1);
            }
        }

        // epilogue: C frag -> g_T
        const int r0 = l >> 2, c0 = (l & 3)*2;
        const size_t base = (size_t)blk*128 + wr;
        #pragma unroll
        for (int nt = 0; nt < 4; nt++) {
            float* p0 = &g_T[(base + r0)*HH + nt*8 + c0];
            float* p1 = &g_T[(base + r0 + 8)*HH + nt*8 + c0];
            *(float2*)p0 = make_float2(c[nt][0], c[nt][1]);
            *(float2*)p1 = make_float2(c[nt][2], c[nt][3]);
        }
    }
    __syncthreads();   // all smem reads done; reuse for the tail

    // ---- tail: node-level layer-1 + precompute u1/v1/s2 ----
    float* sAs2 = sf + TL_AS;
    float* sWn  = sf + TL_WN;
    float* sP   = sf + TL_P;
    float* sQ   = sf + TL_Q;
    float* sW2  = sf + TL_W2;

    *(float4*)&sAs2[w*132 + 4*l] = asum;
    #pragma unroll
    for (int r = 0; r < 16; r++) {
        int idx = tid + 256*r;
        int hh = idx >> 7, k = idx & 127;
        sWn[k*33 + hh] = __ldg(wn1p + idx);
    }
    #pragma unroll
    for (int r = 0; r < 4; r++) {
        int idx = tid + 256*r;
        int hh = idx >> 5, h2 = idx & 31;
        float wa = __ldg(we1p + hh*64 + h2);
        float wb = __ldg(we1p + hh*64 + 32 + h2);
        sP[h2*33 + hh] = 0.5f*(wa + wb);
        sQ[h2*33 + hh] = 0.5f*(wb - wa);
        sW2[h2*33 + hh] = __ldg(wn2s + idx);
    }
    __syncthreads();

    const float invD = 1.0f / __ldg(D + node);
    float s = 0.f;
    #pragma unroll
    for (int k0 = 0; k0 < FIN; k0 += 4) {
        float4 av = *(const float4*)&sAs2[w*132 + k0];
        s = fmaf(av.x, sWn[(k0+0)*33 + l], s);
        s = fmaf(av.y, sWn[(k0+1)*33 + l], s);
        s = fmaf(av.z, sWn[(k0+2)*33 + l], s);
        s = fmaf(av.w, sWn[(k0+3)*33 + l], s);
    }
    float x = fmaxf(fmaf(s, invD, __ldg(bn1p+l) + __ldg(bn1s+l)), 0.f);

    float u  = __ldg(be1p+l) + __ldg(be1s+l);
    float vv = 0.f;
    float s2 = __ldg(bn2p+l) + __ldg(bn2s+l);
    #pragma unroll
    for (int h2 = 0; h2 < 32; h2++) {
        float xx = __shfl_sync(0xffffffffu, x, h2);
        u  = fmaf(xx, sP[h2*33 + l], u);
        vv = fmaf(xx, sQ[h2*33 + l], vv);
        s2 = fmaf(xx, sW2[h2*33 + l], s2);
    }
    g_u1[node*HH + l] = u;
    g_v1[node*HH + l] = vv;
    g_s2[node*HH + l] = s2;
}

// ============================================================================
// K2 (fused edge layer 2 GEMM + node layer 2)
// ============================================================================
__global__ __launch_bounds__(256) void k2(const int* __restrict__ dst,
                                          const float* __restrict__ D,
                                          const float* __restrict__ we2s,
                                          const float* __restrict__ wn2p,
                                          const float* __restrict__ we2p,
                                          const float* __restrict__ be2p,
                                          const float* __restrict__ be2s) {
    __shared__ float sV[128*33];
    __shared__ float sW[32*36];
    __shared__ float sWn[32*33];
    __shared__ float sP[32*33];
    __shared__ float sQ[32*33];
    const int tid = threadIdx.x, blk = blockIdx.x;
    #pragma unroll
    for (int r = 0; r < 4; r++) {
        int idx = tid + 256*r;
        int hh = idx >> 5, h2 = idx & 31;
        sW[h2*36 + hh]  = __ldg(we2s + idx);
        sWn[h2*33 + hh] = __ldg(wn2p + idx);
        float wa = __ldg(we2p + hh*64 + h2);
        float wb = __ldg(we2p + hh*64 + 32 + h2);
        sP[h2*33 + hh] = 0.5f*(wa + wb);
        sQ[h2*33 + hh] = 0.5f*(wb - wa);
    }
    const int w = tid >> 5, h = tid & 31;
    const int node = blk*8 + w;
    const float u1h = g_u1[node*HH + h];
    float asum = 0.f;
    const int* de = dst + node*DEGQ;
    const size_t ebase = (size_t)node*DEGQ;
    __syncthreads();
    #pragma unroll
    for (int j = 0; j < DEGQ; j++) {
        int d = __ldg(de + j);
        float val = u1h + g_v1[d*HH + h] + g_T[(ebase + j)*HH + h];
        val = fmaxf(val, 0.f);
        asum += val;
        sV[(w*DEGQ + j)*33 + h] = val;
    }
    __syncthreads();

    const int tx = tid & 7, ty = tid >> 3;
    unsigned long long acc[4][2];
    #pragma unroll
    for (int i = 0; i < 4; i++) { acc[i][0] = 0ull; acc[i][1] = 0ull; }
    #pragma unroll 4
    for (int h2 = 0; h2 < 32; h2++) {
        ulonglong2 wv = *(const ulonglong2*)&sW[h2*36 + 4*tx];
        #pragma unroll
        for (int i = 0; i < 4; i++) {
            unsigned long long a2 = dup2(sV[(ty + 32*i)*33 + h2]);
            fma2(acc[i][0], a2, wv.x);
            fma2(acc[i][1], a2, wv.y);
        }
    }
    const size_t tb = (size_t)blk*128;
    #pragma unroll
    for (int i = 0; i < 4; i++) {
        ulonglong2 v; v.x = acc[i][0]; v.y = acc[i][1];
        *(ulonglong2*)&g_T[(tb + ty + 32*i)*HH + 4*tx] = v;
    }

    const float invD = 1.0f / __ldg(D + node);
    float s = 0.f;
    #pragma unroll
    for (int h2 = 0; h2 < 32; h2++) {
        float aa = __shfl_sync(0xffffffffu, asum, h2);
        s = fmaf(aa, sWn[h2*33 + h], s);
    }
    float x = fmaxf(fmaf(s, invD, g_s2[node*HH + h]), 0.f);
    float u = __ldg(be2p+h) + __ldg(be2s+h), vv = 0.f;
    #pragma unroll
    for (int h2 = 0; h2 < 32; h2++) {
        float xx = __shfl_sync(0xffffffffu, x, h2);
        u  = fmaf(xx, sP[h2*33 + h], u);
        vv = fmaf(xx, sQ[h2*33 + h], vv);
    }
    g_u2[node*HH + h] = u;
    g_v2[node*HH + h] = vv;
}

// ============================================================================
// K3: out[e] = sigmoid( sum_h relu(u2[src]+v2[dst]+T2[e])*wc[h] + bc )
// ============================================================================
__global__ __launch_bounds__(256) void k3(const int* __restrict__ dst,
                                          const float* __restrict__ wc,
                                          const float* __restrict__ bc,
                                          float* __restrict__ out) {
    const int tid = threadIdx.x, w = tid >> 5, l = tid & 31;
    const size_t e0 = (size_t)blockIdx.x*256 + (size_t)w*32;
    const float wch = __ldg(wc + l);
    float res = 0.f;
    #pragma unroll 4
    for (int m = 0; m < 32; m++) {
        const size_t e = e0 + m;
        const int s = (int)(e >> 4);
        const int d = __ldg(dst + e);
        float val = g_u2[s*HH + l] + g_v2[d*HH + l] + g_T[e*HH + l];
        val = fmaxf(val, 0.f);
        float c = val * wch;
        c += __shfl_xor_sync(0xffffffffu, c, 16);
        c += __shfl_xor_sync(0xffffffffu, c, 8);
        c += __shfl_xor_sync(0xffffffffu, c, 4);
        c += __shfl_xor_sync(0xffffffffu, c, 2);
        c += __shfl_xor_sync(0xffffffffu, c, 1);
        if (l == m) res = c;
    }
    const float x = res + __ldg(bc);
    out[e0 + l] = 1.f / (1.f + __expf(-x));
}

// ============================================================================
extern "C" void kernel_launch(void* const* d_in, const int* in_sizes, int n_in,
                              void* d_out, int out_size) {
    const float* X    = (const float*)d_in[0];
    const int*   dst  = (const int*)  d_in[2];
    const float* D    = (const float*)d_in[3];
    const float* wn1p = (const float*)d_in[4];
    const float* bn1p = (const float*)d_in[5];
    const float* bn1s = (const float*)d_in[7];
    const float* we1p = (const float*)d_in[8];
    const float* be1p = (const float*)d_in[9];
    const float* we1s = (const float*)d_in[10];
    const float* be1s = (const float*)d_in[11];
    const float* wn2p = (const float*)d_in[12];
    const float* bn2p = (const float*)d_in[13];
    const float* wn2s = (const float*)d_in[14];
    const float* bn2s = (const float*)d_in[15];
    const float* we2p = (const float*)d_in[16];
    const float* be2p = (const float*)d_in[17];
    const float* we2s = (const float*)d_in[18];
    const float* be2s = (const float*)d_in[19];
    const float* wc   = (const float*)d_in[20];
    const float* bc   = (const float*)d_in[21];
    float* out = (float*)d_out;

    cudaFuncSetAttribute(k1, cudaFuncAttributeMaxDynamicSharedMemorySize, K1_SMEM);

    k1 <<<NN/8, 256, K1_SMEM>>>(X, dst, D, we1s, wn1p, bn1p, bn1s,
                                we1p, be1p, be1s, wn2s, bn2p, bn2s);
    k2 <<<NN/8, 256>>>(dst, D, we2s, wn2p, we2p, be2p, be2s);
    k3 <<<EE/256, 256>>>(dst, wc, bc, out);
}